// round 10
// baseline (speedup 1.0000x reference)
#include <cuda_runtime.h>
#include <cstdint>

#define NB 8
#define CB 16
#define HB 256
#define WB 256
#define TOT (NB*CB*HB*WB)   // 8388608
#define IDX_OFF (TOT + 91)

#define TJ 64               // output tile width  (j)
#define TI 8                // output tile height (i)
#define NTHR 128            // 4 warps; warp w -> output rows 2w, 2w+1
#define PCOLS 68            // 66 used (TJ+2 halo), padded
#define PROWS (TI+2)        // 10
#define PSZ (PROWS*PCOLS)
#define NELEM (PROWS*66)    // 660 plane elements
#define KPT 6               // ceil(660/128) staged loads per thread
#define SLOTS 512

__device__ float2 g_mm[SLOTS];   // per-block (min,max) partials

// ---------------------------------------------------------------------------
// Per-block min/max partials; block 0 passes through co_matrix & filter.
// ---------------------------------------------------------------------------
__global__ void __launch_bounds__(256)
minmax_kernel(const float4* __restrict__ x, int n4,
              const float* __restrict__ co,
              const float* __restrict__ filt,
              float* __restrict__ out) {
    if (blockIdx.x == 0) {
        int t = threadIdx.x;
        if (t < 64) out[TOT + t] = co[t];
        if (t < 27) out[TOT + 64 + t] = filt[t];
    }
    float lmin = __int_as_float(0x7f800000);
    float lmax = 0.0f;
    int stride = gridDim.x * blockDim.x;
    for (int i = blockIdx.x * blockDim.x + threadIdx.x; i < n4; i += stride) {
        float4 v = x[i];
        lmin = fminf(lmin, fminf(fminf(v.x, v.y), fminf(v.z, v.w)));
        lmax = fmaxf(lmax, fmaxf(fmaxf(v.x, v.y), fmaxf(v.z, v.w)));
    }
#pragma unroll
    for (int o = 16; o; o >>= 1) {
        lmin = fminf(lmin, __shfl_xor_sync(0xffffffffu, lmin, o));
        lmax = fmaxf(lmax, __shfl_xor_sync(0xffffffffu, lmax, o));
    }
    __shared__ float smin[8], smax[8];
    int w = threadIdx.x >> 5;
    if ((threadIdx.x & 31) == 0) { smin[w] = lmin; smax[w] = lmax; }
    __syncthreads();
    if (threadIdx.x < 8) {
        lmin = smin[threadIdx.x];
        lmax = smax[threadIdx.x];
#pragma unroll
        for (int o = 4; o; o >>= 1) {
            lmin = fminf(lmin, __shfl_xor_sync(0xffu, lmin, o));
            lmax = fmaxf(lmax, __shfl_xor_sync(0xffu, lmax, o));
        }
        if (threadIdx.x == 0) g_mm[blockIdx.x] = make_float2(lmin, lmax);
    }
}

// ---------------------------------------------------------------------------
__device__ __forceinline__ uint32_t smem_u32(const void* p) {
    uint32_t a;
    asm("{ .reg .u64 t; cvta.to.shared.u64 t, %1; cvt.u32.u64 %0, t; }"
        : "=r"(a) : "l"(p));
    return a;
}

// fused-table gathers: addr = (w & 0x1C) | rbd, LDS at immediate d-offset.
// rbd = Tbase + r*32 + d0*256 has bits [4:0] clear -> OR via one LOP3.
__device__ __forceinline__ float g0(uint32_t w, uint32_t rbd) {
    uint32_t a; float v;
    asm("lop3.b32 %0, %1, 0x1C, %2, 0xEA;" : "=r"(a) : "r"(w), "r"(rbd));
    asm("ld.shared.f32 %0, [%1];" : "=f"(v) : "r"(a));
    return v;
}
__device__ __forceinline__ float g1(uint32_t w, uint32_t rbd) {
    uint32_t a; float v;
    asm("lop3.b32 %0, %1, 0x1C, %2, 0xEA;" : "=r"(a) : "r"(w), "r"(rbd));
    asm("ld.shared.f32 %0, [%1+256];" : "=f"(v) : "r"(a));
    return v;
}
__device__ __forceinline__ float g2(uint32_t w, uint32_t rbd) {
    uint32_t a; float v;
    asm("lop3.b32 %0, %1, 0x1C, %2, 0xEA;" : "=r"(a) : "r"(w), "r"(rbd));
    asm("ld.shared.f32 %0, [%1+512];" : "=f"(v) : "r"(a));
    return v;
}

// ---------------------------------------------------------------------------
// out[n,c,i,j] = [idx_p<8] * sum_{27 nbr} filt_d * co[idx_p, clamp(idx_nbr,7)] * x_nbr
//
// KEY (this round): single fused smem table T[d][r][c] = filt[d]*co[r][c]
// (27*64 words = 6.9 KB, no lane replication). Per tap:
//    LOP3 (column bits from packed word) + LDS[+d*256 imm] + FFMA(T, x)
// = 3 instructions (the per-tap FMUL and the filter operand are gone).
// Packed plane word: x mantissa bits [5:2] = clamped column (pre-shifted
// byte offset), bit [5]... col at [4:2], flag (idx==8) at [5]; perturbation
// <= 4e-6 relative. Conflicts only when lanes hit (r, c) vs (r^4, c): rare.
// ---------------------------------------------------------------------------
__global__ void __launch_bounds__(NTHR)
cooc_kernel(const float* __restrict__ x,
            const float* __restrict__ co,
            const float* __restrict__ filt,
            float* __restrict__ out) {
    __shared__ __align__(16) unsigned planes[4][PSZ];   // ~10.9 KB
    __shared__ __align__(128) float T[27 * 64];         // 6.9 KB fused LUT
    __shared__ float s_red[16];      // [0..3] warp mins, [8..11] warp maxs
    __shared__ float s_mm[2];

    const int tid  = threadIdx.x;
    const int lane = tid & 31;
    const int wrp  = tid >> 5;       // 0..3

    const int j0 = blockIdx.x * TJ;
    const int i0 = blockIdx.y * TI;
    const int n  = blockIdx.z;

    // ---- reduce min/max partials (512 slots, 4 per thread, 4 warps) ----
    {
        float2 a = g_mm[tid];
        float2 b = g_mm[tid + 128];
        float2 c = g_mm[tid + 256];
        float2 d = g_mm[tid + 384];
        float mn = fminf(fminf(a.x, b.x), fminf(c.x, d.x));
        float mx = fmaxf(fmaxf(a.y, b.y), fmaxf(c.y, d.y));
#pragma unroll
        for (int o = 16; o; o >>= 1) {
            mn = fminf(mn, __shfl_xor_sync(0xffffffffu, mn, o));
            mx = fmaxf(mx, __shfl_xor_sync(0xffffffffu, mx, o));
        }
        if (lane == 0) { s_red[wrp] = mn; s_red[8 + wrp] = mx; }
    }

    // ---- build fused table T[d][r][c] = filt[d] * co[r*8+c] ----
    for (int e = tid; e < 27 * 64; e += NTHR)
        T[e] = filt[e >> 6] * co[e & 63];
    const uint32_t Tb = smem_u32(T);

    __syncthreads();
    // only the 4 written slots per side are read (4 warps)
    if (tid < 2) {
        float v;
        if (tid == 0) v = fminf(fminf(s_red[0], s_red[1]), fminf(s_red[2], s_red[3]));
        else          v = fmaxf(fmaxf(s_red[8], s_red[9]), fmaxf(s_red[10], s_red[11]));
        s_mm[tid] = v;
    }
    __syncthreads();
    const float xmin = s_mm[0];
    const float xmax = s_mm[1];

    const float* xb = x + (size_t)n * (CB * HB * WB);

    auto pack = [&](float xv) -> unsigned {
        // exact JAX rounding: ((x - min) / max) * 8, floor
        float t = __fdiv_rn(xv - xmin, xmax) * 8.0f;
        int q = (int)t;                               // q in [0, 8]
        unsigned qc = (q < 8) ? (unsigned)q : 7u;     // clamped col
        unsigned fl = (q >= 8) ? 1u : 0u;             // idx==8 flag
        return (__float_as_uint(xv) & ~0x3Fu) | (qc << 2) | (fl << 5);
    };

    // ---- per-thread prefetch element geometry (channel-invariant) ----
    int  goff[KPT];
    int  soff[KPT];
    bool evalid[KPT];
#pragma unroll
    for (int k = 0; k < KPT; k++) {
        int e = tid + 128 * k;
        int r = e / 66;
        int c = e - r * 66;
        int gi = i0 - 1 + r;
        int gj = j0 - 1 + c;
        bool ok = (e < NELEM) && ((unsigned)gi < (unsigned)HB) &&
                  ((unsigned)gj < (unsigned)WB);
        goff[k]   = ok ? (gi * WB + gj) : 0;
        soff[k]   = r * PCOLS + c;
        evalid[k] = ok;
    }

    // prologue: planes -1, 0, 1 (plane p lives in buf (p+1)&3)
    for (int p = -1; p <= 1; p++) {
        unsigned* B = planes[(p + 1) & 3];
        const float* src = xb + p * (HB * WB);
#pragma unroll
        for (int k = 0; k < KPT; k++) {
            if (tid + 128 * k < NELEM) {
                unsigned pv = 0u;
                if (p >= 0 && evalid[k]) pv = pack(src[goff[k]]);
                B[soff[k]] = pv;
            }
        }
    }

    const int rowbase = 2 * wrp;
    const int gi0     = i0 + 2 * wrp;
    const int jb      = j0 + 2 * lane;

    for (int ci = 0; ci < CB; ci++) {
        __syncthreads();

        // stage LDGs for plane ci+2 (consumed only after compute)
        float sv[KPT];
        const bool do_pref  = (ci <= CB - 2);
        const bool in_range = (ci + 2 < CB);
        if (do_pref && in_range) {
            const float* src = xb + (ci + 2) * (HB * WB);
#pragma unroll
            for (int k = 0; k < KPT; k++)
                sv[k] = evalid[k] ? src[goff[k]] : 0.0f;
        }

        // center words -> per-output row bases into T (r*32 = (w&0x1C)<<3)
        const unsigned* Pc = planes[(ci + 1) & 3] + rowbase * PCOLS + 2 * lane;
        uint2 c1a = *(const uint2*)(Pc + 1 * PCOLS);
        uint2 c1b = *(const uint2*)(Pc + 1 * PCOLS + 2);
        uint2 c2a = *(const uint2*)(Pc + 2 * PCOLS);
        uint2 c2b = *(const uint2*)(Pc + 2 * PCOLS + 2);
        const unsigned cw00 = c1a.y, cw01 = c1b.x;
        const unsigned cw10 = c2a.y, cw11 = c2b.x;
        const uint32_t rb00 = Tb + ((cw00 & 0x1Cu) << 3);
        const uint32_t rb01 = Tb + ((cw01 & 0x1Cu) << 3);
        const uint32_t rb10 = Tb + ((cw10 & 0x1Cu) << 3);
        const uint32_t rb11 = Tb + ((cw11 & 0x1Cu) << 3);

        float a00 = 0.f, a01 = 0.f, a10 = 0.f, a11 = 0.f;

#pragma unroll
        for (int dc = 0; dc < 3; dc++) {
            const unsigned* P = planes[(ci + dc) & 3] + rowbase * PCOLS + 2 * lane;
#pragma unroll
            for (int r = 0; r < 4; r++) {
                uint2 A  = *(const uint2*)(P + r * PCOLS);
                uint2 Bv = *(const uint2*)(P + r * PCOLS + 2);
                unsigned w0 = A.x, w1 = A.y, w2 = Bv.x, w3 = Bv.y;
                if (r <= 2) {
                    const uint32_t d0 = (uint32_t)((dc * 9 + r * 3) * 256);
                    const uint32_t p0 = rb00 + d0;
                    const uint32_t p1 = rb01 + d0;
                    a00 = fmaf(g0(w0, p0), __uint_as_float(w0), a00);
                    a00 = fmaf(g1(w1, p0), __uint_as_float(w1), a00);
                    a00 = fmaf(g2(w2, p0), __uint_as_float(w2), a00);
                    a01 = fmaf(g0(w1, p1), __uint_as_float(w1), a01);
                    a01 = fmaf(g1(w2, p1), __uint_as_float(w2), a01);
                    a01 = fmaf(g2(w3, p1), __uint_as_float(w3), a01);
                }
                if (r >= 1) {
                    const uint32_t d0 = (uint32_t)((dc * 9 + (r - 1) * 3) * 256);
                    const uint32_t p0 = rb10 + d0;
                    const uint32_t p1 = rb11 + d0;
                    a10 = fmaf(g0(w0, p0), __uint_as_float(w0), a10);
                    a10 = fmaf(g1(w1, p0), __uint_as_float(w1), a10);
                    a10 = fmaf(g2(w2, p0), __uint_as_float(w2), a10);
                    a11 = fmaf(g0(w1, p1), __uint_as_float(w1), a11);
                    a11 = fmaf(g1(w2, p1), __uint_as_float(w2), a11);
                    a11 = fmaf(g2(w3, p1), __uint_as_float(w3), a11);
                }
            }
        }

        const int o0 = ((n * CB + ci) * HB + gi0) * WB + jb;
        const int o1 = o0 + WB;
        float2 r0v, r1v;
        r0v.x = (cw00 & 0x20u) ? 0.0f : a00;
        r0v.y = (cw01 & 0x20u) ? 0.0f : a01;
        r1v.x = (cw10 & 0x20u) ? 0.0f : a10;
        r1v.y = (cw11 & 0x20u) ? 0.0f : a11;
        *(float2*)(out + o0) = r0v;
        *(float2*)(out + o1) = r1v;
        // raw idx = clamped col + flag
        out[IDX_OFF + o0]     = (float)(((cw00 >> 2) & 7u) + ((cw00 >> 5) & 1u));
        out[IDX_OFF + o0 + 1] = (float)(((cw01 >> 2) & 7u) + ((cw01 >> 5) & 1u));
        out[IDX_OFF + o1]     = (float)(((cw10 >> 2) & 7u) + ((cw10 >> 5) & 1u));
        out[IDX_OFF + o1 + 1] = (float)(((cw11 >> 2) & 7u) + ((cw11 >> 5) & 1u));

        // drain: pack staged values, store plane ci+2 into buf (ci+3)&3
        // (its old content, plane ci-2, was last read in iter ci-1 before
        //  the top-of-iteration sync -> race-free with 4 buffers)
        if (do_pref) {
            unsigned* B = planes[(ci + 3) & 3];
#pragma unroll
            for (int k = 0; k < KPT; k++) {
                if (tid + 128 * k < NELEM) {
                    unsigned pv = 0u;
                    if (in_range && evalid[k]) pv = pack(sv[k]);
                    B[soff[k]] = pv;
                }
            }
        }
    }
}

// ---------------------------------------------------------------------------
extern "C" void kernel_launch(void* const* d_in, const int* in_sizes, int n_in,
                              void* d_out, int out_size) {
    const float* x    = (const float*)d_in[0];
    const float* co   = (const float*)d_in[1];
    const float* filt = (const float*)d_in[2];
    float* out        = (float*)d_out;

    minmax_kernel<<<SLOTS, 256>>>((const float4*)x, TOT / 4, co, filt, out);

    dim3 grid(WB / TJ, HB / TI, NB);   // 4 x 32 x 8 = 1024 blocks
    cooc_kernel<<<grid, NTHR>>>(x, co, filt, out);
}

// round 11
// speedup vs baseline: 1.2702x; 1.2702x over previous
#include <cuda_runtime.h>
#include <cstdint>

#define NB 8
#define CB 16
#define HB 256
#define WB 256
#define TOT (NB*CB*HB*WB)   // 8388608
#define IDX_OFF (TOT + 91)

#define TJ 64               // output tile width  (j)
#define TI 8                // output tile height (i)
#define NTHR 128            // 4 warps; warp w -> output rows 2w, 2w+1
#define PCOLS 68            // 66 used (TJ+2 halo), padded
#define PROWS (TI+2)        // 10
#define PSZ (PROWS*PCOLS)
#define NELEM (PROWS*66)    // 660 plane elements
#define KPT 6               // ceil(660/128) prefetch elems per thread
#define NBUF 7
#define SLOTS 512

__device__ float2 g_mm[SLOTS];   // per-block (min,max) partials

// ---------------------------------------------------------------------------
__global__ void __launch_bounds__(256)
minmax_kernel(const float4* __restrict__ x, int n4,
              const float* __restrict__ co,
              const float* __restrict__ filt,
              float* __restrict__ out) {
    if (blockIdx.x == 0) {
        int t = threadIdx.x;
        if (t < 64) out[TOT + t] = co[t];
        if (t < 27) out[TOT + 64 + t] = filt[t];
    }
    float lmin = __int_as_float(0x7f800000);
    float lmax = 0.0f;
    int stride = gridDim.x * blockDim.x;
    for (int i = blockIdx.x * blockDim.x + threadIdx.x; i < n4; i += stride) {
        float4 v = x[i];
        lmin = fminf(lmin, fminf(fminf(v.x, v.y), fminf(v.z, v.w)));
        lmax = fmaxf(lmax, fmaxf(fmaxf(v.x, v.y), fmaxf(v.z, v.w)));
    }
#pragma unroll
    for (int o = 16; o; o >>= 1) {
        lmin = fminf(lmin, __shfl_xor_sync(0xffffffffu, lmin, o));
        lmax = fmaxf(lmax, __shfl_xor_sync(0xffffffffu, lmax, o));
    }
    __shared__ float smin[8], smax[8];
    int w = threadIdx.x >> 5;
    if ((threadIdx.x & 31) == 0) { smin[w] = lmin; smax[w] = lmax; }
    __syncthreads();
    if (threadIdx.x < 8) {
        lmin = smin[threadIdx.x];
        lmax = smax[threadIdx.x];
#pragma unroll
        for (int o = 4; o; o >>= 1) {
            lmin = fminf(lmin, __shfl_xor_sync(0xffu, lmin, o));
            lmax = fmaxf(lmax, __shfl_xor_sync(0xffu, lmax, o));
        }
        if (threadIdx.x == 0) g_mm[blockIdx.x] = make_float2(lmin, lmax);
    }
}

// ---------------------------------------------------------------------------
__device__ __forceinline__ uint32_t smem_u32(const void* p) {
    uint32_t a;
    asm("{ .reg .u64 t; cvta.to.shared.u64 t, %1; cvt.u32.u64 %0, t; }"
        : "=r"(a) : "l"(p));
    return a;
}

// co gather: addr = (w & 0x380) | rbase -> one LOP3, then LDS (bank = lane).
__device__ __forceinline__ float co_gather(uint32_t w, uint32_t rbase) {
    uint32_t a; float v;
    asm("lop3.b32 %0, %1, 0x380, %2, 0xEA;" : "=r"(a) : "r"(w), "r"(rbase));
    asm("ld.shared.f32 %0, [%1];" : "=f"(v) : "r"(a));
    return v;
}

// ---------------------------------------------------------------------------
// out[n,c,i,j] = [idx_p<8] * sum_{27} filt * co[idx_p, clamp(idx_nbr,7)] * x_nbr
//
// Packed word: x mantissa bits [9:7] = clamped column (pre-shifted byte
// offset for the 128B column stride), bit [10] = (idx==8) flag.
// co table: 8 rows x 8 cols x 32 lane replicas (8 KB), conflict-free.
//
// KEY (this round): TWO channels per iteration. Channels (ci, ci+1) are
// computed together from planes ci-1..ci+2 held in a 7-buffer ring:
//   - one __syncthreads per 2 channels
//   - interior planes read 2x total (was 3x)
//   - LDG latency exposed once per 2 channels
// Ring safety: read bufs = base..base+3, write bufs = base+4, base+5
// (mod 7, disjoint); overwritten planes last read >= 2 iterations ago.
// ---------------------------------------------------------------------------
__global__ void __launch_bounds__(NTHR)
cooc_kernel(const float* __restrict__ x,
            const float* __restrict__ co,
            const float* __restrict__ filt,
            float* __restrict__ out) {
    __shared__ __align__(16) unsigned planes[NBUF][PSZ];  // ~18.6 KB
    __shared__ float co_pad[2048 + 256];                  // 8 KB + align pad
    __shared__ float s_red[16];
    __shared__ float s_mm[2];

    const int tid  = threadIdx.x;
    const int lane = tid & 31;
    const int wrp  = tid >> 5;

    const int j0 = blockIdx.x * TJ;
    const int i0 = blockIdx.y * TI;
    const int n  = blockIdx.z;

    // ---- reduce min/max partials ----
    {
        float2 a = g_mm[tid];
        float2 b = g_mm[tid + 128];
        float2 c = g_mm[tid + 256];
        float2 d = g_mm[tid + 384];
        float mn = fminf(fminf(a.x, b.x), fminf(c.x, d.x));
        float mx = fmaxf(fmaxf(a.y, b.y), fmaxf(c.y, d.y));
#pragma unroll
        for (int o = 16; o; o >>= 1) {
            mn = fminf(mn, __shfl_xor_sync(0xffffffffu, mn, o));
            mx = fmaxf(mx, __shfl_xor_sync(0xffffffffu, mx, o));
        }
        if (lane == 0) { s_red[wrp] = mn; s_red[8 + wrp] = mx; }
    }

    // ---- replicated co LUT ----
    uintptr_t gp = (uintptr_t)co_pad;
    float* co_rep = (float*)((gp + 1023) & ~(uintptr_t)1023);
    const uint32_t co_u32 = smem_u32(co_rep);
    for (int e = tid; e < 2048; e += NTHR) {
        int l = e & 31;
        int c = (e >> 5) & 7;
        int r = e >> 8;
        co_rep[r * 256 + c * 32 + l] = co[r * 8 + c];
    }

    // ---- filter -> registers (fenced) ----
    float fr[27];
#pragma unroll
    for (int k = 0; k < 27; k++) {
        float v = filt[k];
        asm("mov.f32 %0, %0;" : "+f"(v));
        fr[k] = v;
    }

    __syncthreads();
    if (tid < 2) {
        float v;
        if (tid == 0) v = fminf(fminf(s_red[0], s_red[1]), fminf(s_red[2], s_red[3]));
        else          v = fmaxf(fmaxf(s_red[8], s_red[9]), fmaxf(s_red[10], s_red[11]));
        s_mm[tid] = v;
    }
    __syncthreads();
    const float xmin = s_mm[0];
    const float xmax = s_mm[1];

    const float* xb = x + (size_t)n * (CB * HB * WB);

    auto pack = [&](float xv) -> unsigned {
        float t = __fdiv_rn(xv - xmin, xmax) * 8.0f;   // exact JAX rounding
        int q = (int)t;                                 // [0, 8]
        unsigned qc = (q < 8) ? (unsigned)q : 7u;
        unsigned fl = (q >= 8) ? 1u : 0u;
        return (__float_as_uint(xv) & ~0x780u) | (qc << 7) | (fl << 10);
    };

    // ---- channel-invariant prefetch geometry ----
    int  goff[KPT];
    int  soff[KPT];
    bool evalid[KPT];
#pragma unroll
    for (int k = 0; k < KPT; k++) {
        int e = tid + 128 * k;
        int r = e / 66;
        int c = e - r * 66;
        int gi = i0 - 1 + r;
        int gj = j0 - 1 + c;
        bool ok = (e < NELEM) && ((unsigned)gi < (unsigned)HB) &&
                  ((unsigned)gj < (unsigned)WB);
        goff[k]   = ok ? (gi * WB + gj) : 0;
        soff[k]   = r * PCOLS + c;
        evalid[k] = ok;
    }

    auto load_plane = [&](int cc, int buf) {
        unsigned* B = planes[buf];
        if ((unsigned)cc < (unsigned)CB) {
            const float* src = xb + cc * (HB * WB);
#pragma unroll
            for (int k = 0; k < KPT; k++) {
                if (tid + 128 * k < NELEM) {
                    unsigned pv = evalid[k] ? pack(src[goff[k]]) : 0u;
                    B[soff[k]] = pv;
                }
            }
        } else {
#pragma unroll
            for (int k = 0; k < KPT; k++)
                if (tid + 128 * k < NELEM) B[soff[k]] = 0u;
        }
    };

    // prologue: planes -1,0,1,2 -> bufs 0..3  (plane p -> buf (p+1) mod 7)
    load_plane(-1, 0);
    load_plane(0, 1);
    load_plane(1, 2);
    load_plane(2, 3);

    const int rowbase = 2 * wrp;
    const int gi0     = i0 + 2 * wrp;
    const int jb      = j0 + 2 * lane;
    const uint32_t lanebase = co_u32 + (lane << 2);

    auto tap3 = [&](float& acc, uint32_t rb, int fo,
                    unsigned p0, unsigned p1, unsigned p2) {
        acc = fmaf(fr[fo + 0], co_gather(p0, rb) * __uint_as_float(p0), acc);
        acc = fmaf(fr[fo + 1], co_gather(p1, rb) * __uint_as_float(p1), acc);
        acc = fmaf(fr[fo + 2], co_gather(p2, rb) * __uint_as_float(p2), acc);
    };

    int base = 0;   // buf index of plane ci-1  ( = ci mod 7 )
    for (int it = 0; it < CB / 2; it++) {
        const int ci = 2 * it;
        __syncthreads();

        // ---- prefetch planes ci+3, ci+4 into bufs base+4, base+5 ----
        if (it < CB / 2 - 1) {
            int b4 = base + 4; if (b4 >= NBUF) b4 -= NBUF;
            int b5 = base + 5; if (b5 >= NBUF) b5 -= NBUF;
            load_plane(ci + 3, b4);
            load_plane(ci + 4, b5);
        }

        int bA = base + 1; if (bA >= NBUF) bA -= NBUF;   // plane ci
        int bB = base + 2; if (bB >= NBUF) bB -= NBUF;   // plane ci+1

        // ---- centers for both channels ----
        const unsigned* Pa = planes[bA] + rowbase * PCOLS + 2 * lane;
        const unsigned* Pb = planes[bB] + rowbase * PCOLS + 2 * lane;
        uint2 a1 = *(const uint2*)(Pa + 1 * PCOLS);
        uint2 a1h = *(const uint2*)(Pa + 1 * PCOLS + 2);
        uint2 a2 = *(const uint2*)(Pa + 2 * PCOLS);
        uint2 a2h = *(const uint2*)(Pa + 2 * PCOLS + 2);
        uint2 b1 = *(const uint2*)(Pb + 1 * PCOLS);
        uint2 b1h = *(const uint2*)(Pb + 1 * PCOLS + 2);
        uint2 b2 = *(const uint2*)(Pb + 2 * PCOLS);
        uint2 b2h = *(const uint2*)(Pb + 2 * PCOLS + 2);
        const unsigned cw00 = a1.y, cw01 = a1h.x, cw10 = a2.y, cw11 = a2h.x;
        const unsigned dw00 = b1.y, dw01 = b1h.x, dw10 = b2.y, dw11 = b2h.x;
        const uint32_t rb00 = lanebase + ((cw00 & 0x380u) << 3);
        const uint32_t rb01 = lanebase + ((cw01 & 0x380u) << 3);
        const uint32_t rb10 = lanebase + ((cw10 & 0x380u) << 3);
        const uint32_t rb11 = lanebase + ((cw11 & 0x380u) << 3);
        const uint32_t sb00 = lanebase + ((dw00 & 0x380u) << 3);
        const uint32_t sb01 = lanebase + ((dw01 & 0x380u) << 3);
        const uint32_t sb10 = lanebase + ((dw10 & 0x380u) << 3);
        const uint32_t sb11 = lanebase + ((dw11 & 0x380u) << 3);

        float a00 = 0.f, a01 = 0.f, a10 = 0.f, a11 = 0.f;   // channel ci
        float b00 = 0.f, b01 = 0.f, b10 = 0.f, b11 = 0.f;   // channel ci+1

#pragma unroll
        for (int pi = 0; pi < 4; pi++) {      // plane ci-1+pi
            int bp = base + pi; if (bp >= NBUF) bp -= NBUF;
            const unsigned* P = planes[bp] + rowbase * PCOLS + 2 * lane;
#pragma unroll
            for (int r = 0; r < 4; r++) {
                uint2 A  = *(const uint2*)(P + r * PCOLS);
                uint2 Bv = *(const uint2*)(P + r * PCOLS + 2);
                unsigned w0 = A.x, w1 = A.y, w2 = Bv.x, w3 = Bv.y;
                if (pi <= 2) {                 // channel ci, dc = pi
                    if (r <= 2) {
                        tap3(a00, rb00, pi * 9 + r * 3, w0, w1, w2);
                        tap3(a01, rb01, pi * 9 + r * 3, w1, w2, w3);
                    }
                    if (r >= 1) {
                        tap3(a10, rb10, pi * 9 + (r - 1) * 3, w0, w1, w2);
                        tap3(a11, rb11, pi * 9 + (r - 1) * 3, w1, w2, w3);
                    }
                }
                if (pi >= 1) {                 // channel ci+1, dc = pi-1
                    if (r <= 2) {
                        tap3(b00, sb00, (pi - 1) * 9 + r * 3, w0, w1, w2);
                        tap3(b01, sb01, (pi - 1) * 9 + r * 3, w1, w2, w3);
                    }
                    if (r >= 1) {
                        tap3(b10, sb10, (pi - 1) * 9 + (r - 1) * 3, w0, w1, w2);
                        tap3(b11, sb11, (pi - 1) * 9 + (r - 1) * 3, w1, w2, w3);
                    }
                }
            }
        }

        // ---- stores: channel ci ----
        const int o0 = ((n * CB + ci) * HB + gi0) * WB + jb;
        const int o1 = o0 + WB;
        {
            float2 r0v, r1v;
            r0v.x = (cw00 & 0x400u) ? 0.0f : a00;
            r0v.y = (cw01 & 0x400u) ? 0.0f : a01;
            r1v.x = (cw10 & 0x400u) ? 0.0f : a10;
            r1v.y = (cw11 & 0x400u) ? 0.0f : a11;
            *(float2*)(out + o0) = r0v;
            *(float2*)(out + o1) = r1v;
            out[IDX_OFF + o0]     = (float)(((cw00 >> 7) & 7u) + ((cw00 >> 10) & 1u));
            out[IDX_OFF + o0 + 1] = (float)(((cw01 >> 7) & 7u) + ((cw01 >> 10) & 1u));
            out[IDX_OFF + o1]     = (float)(((cw10 >> 7) & 7u) + ((cw10 >> 10) & 1u));
            out[IDX_OFF + o1 + 1] = (float)(((cw11 >> 7) & 7u) + ((cw11 >> 10) & 1u));
        }
        // ---- stores: channel ci+1 ----
        const int p0 = o0 + HB * WB;
        const int p1 = p0 + WB;
        {
            float2 r0v, r1v;
            r0v.x = (dw00 & 0x400u) ? 0.0f : b00;
            r0v.y = (dw01 & 0x400u) ? 0.0f : b01;
            r1v.x = (dw10 & 0x400u) ? 0.0f : b10;
            r1v.y = (dw11 & 0x400u) ? 0.0f : b11;
            *(float2*)(out + p0) = r0v;
            *(float2*)(out + p1) = r1v;
            out[IDX_OFF + p0]     = (float)(((dw00 >> 7) & 7u) + ((dw00 >> 10) & 1u));
            out[IDX_OFF + p0 + 1] = (float)(((dw01 >> 7) & 7u) + ((dw01 >> 10) & 1u));
            out[IDX_OFF + p1]     = (float)(((dw10 >> 7) & 7u) + ((dw10 >> 10) & 1u));
            out[IDX_OFF + p1 + 1] = (float)(((dw11 >> 7) & 7u) + ((dw11 >> 10) & 1u));
        }

        base += 2; if (base >= NBUF) base -= NBUF;
    }
}

// ---------------------------------------------------------------------------
extern "C" void kernel_launch(void* const* d_in, const int* in_sizes, int n_in,
                              void* d_out, int out_size) {
    const float* x    = (const float*)d_in[0];
    const float* co   = (const float*)d_in[1];
    const float* filt = (const float*)d_in[2];
    float* out        = (float*)d_out;

    minmax_kernel<<<SLOTS, 256>>>((const float4*)x, TOT / 4, co, filt, out);

    dim3 grid(WB / TJ, HB / TI, NB);   // 4 x 32 x 8 = 1024 blocks
    cooc_kernel<<<grid, NTHR>>>(x, co, filt, out);
}